// round 1
// baseline (speedup 1.0000x reference)
#include <cuda_runtime.h>

#define CB    2
#define CHW   4096
#define CHID  1280
#define CCAD  2048
#define CLTXT 77
#define CNT   4
#define CNH   20
#define CD    64
#define CENCL (CLTXT + CNT)   // 81

// ---------------- scratch (device globals: no allocs allowed) ----------------
__device__ float g_attn[(size_t)CB * CHW * CHID];   // attention output (8192 x 1280)
__device__ float g_k [CB * CLTXT * CHID];
__device__ float g_v [CB * CLTXT * CHID];
__device__ float g_kn[CB * CNT   * CHID];
__device__ float g_vn[CB * CNT   * CHID];

// ---------------- generic 64x64-tile fp32 GEMM: C = A @ W (+bias) ----------------
// A: M x K (row stride lda), W: K x N row-major, C: M x N (row stride ldc)
// grid: (ceil(M/64), N/64), block: 256 threads, 4x4 register tile per thread.
__global__ __launch_bounds__(256) void gemm64(
    const float* __restrict__ A, int M, int K, int lda,
    const float* __restrict__ W, int N,
    float* __restrict__ C, int ldc,
    const float* __restrict__ bias)
{
    __shared__ float As[16][65];
    __shared__ float Ws[16][64];
    const int row0 = blockIdx.x * 64;
    const int col0 = blockIdx.y * 64;
    const int tid = threadIdx.x;
    const int tx = tid & 15, ty = tid >> 4;
    const int ar = tid >> 2, ak = (tid & 3) << 2;   // A-tile load: 64 rows x 16 k
    const int wk = tid >> 4, wc = (tid & 15) << 2;  // W-tile load: 16 k x 64 cols
    const bool arow_ok = (row0 + ar) < M;
    const float* Aptr = A + (size_t)(row0 + ar) * lda + ak;
    const float* Wptr = W + (size_t)wk * N + col0 + wc;

    float acc[4][4] = {};
    for (int k0 = 0; k0 < K; k0 += 16) {
        float4 av = make_float4(0.f, 0.f, 0.f, 0.f);
        if (arow_ok) av = *(const float4*)(Aptr + k0);
        As[ak + 0][ar] = av.x; As[ak + 1][ar] = av.y;
        As[ak + 2][ar] = av.z; As[ak + 3][ar] = av.w;
        *(float4*)&Ws[wk][wc] = *(const float4*)(Wptr + (size_t)k0 * N);
        __syncthreads();
#pragma unroll
        for (int kk = 0; kk < 16; kk++) {
            const float a0 = As[kk][ty * 4 + 0];
            const float a1 = As[kk][ty * 4 + 1];
            const float a2 = As[kk][ty * 4 + 2];
            const float a3 = As[kk][ty * 4 + 3];
            const float4 b4 = *(const float4*)&Ws[kk][tx * 4];
            acc[0][0] += a0 * b4.x; acc[0][1] += a0 * b4.y; acc[0][2] += a0 * b4.z; acc[0][3] += a0 * b4.w;
            acc[1][0] += a1 * b4.x; acc[1][1] += a1 * b4.y; acc[1][2] += a1 * b4.z; acc[1][3] += a1 * b4.w;
            acc[2][0] += a2 * b4.x; acc[2][1] += a2 * b4.y; acc[2][2] += a2 * b4.z; acc[2][3] += a2 * b4.w;
            acc[3][0] += a3 * b4.x; acc[3][1] += a3 * b4.y; acc[3][2] += a3 * b4.z; acc[3][3] += a3 * b4.w;
        }
        __syncthreads();
    }
    float b0 = 0.f, b1 = 0.f, b2 = 0.f, b3 = 0.f;
    if (bias) {
        b0 = bias[col0 + tx * 4 + 0]; b1 = bias[col0 + tx * 4 + 1];
        b2 = bias[col0 + tx * 4 + 2]; b3 = bias[col0 + tx * 4 + 3];
    }
#pragma unroll
    for (int i = 0; i < 4; i++) {
        const int r = row0 + ty * 4 + i;
        if (r < M) {
            float4 o;
            o.x = acc[i][0] + b0; o.y = acc[i][1] + b1;
            o.z = acc[i][2] + b2; o.w = acc[i][3] + b3;
            *(float4*)(C + (size_t)r * ldc + col0 + tx * 4) = o;
        }
    }
}

// ---------------- fused Q-projection + nested attention ----------------
struct SmemQA {
    float As[16][65];
    float Ws[16][64];
    float Qs[64][68];        // scaled q tile (64 tokens x 64 dims), pad 68 for f4 loads
    float Ks[CLTXT][68];
    float Vs[CLTXT][68];
    float KNs[CNT][64];
    float VNs[CNT][64];
    float Wbuf[8][80];       // per-warp softmax weights over 77 keys
};

// grid: (128 token-tiles [b*64 + tile], 20 heads), block 256
__global__ __launch_bounds__(256) void qattn(
    const float* __restrict__ hidden,
    const float* __restrict__ Wq,
    const int* __restrict__ idx_alter)
{
    extern __shared__ char smem_raw[];
    SmemQA& S = *reinterpret_cast<SmemQA*>(smem_raw);
    const int b  = blockIdx.x >> 6;
    const int t0 = (blockIdx.x & 63) << 6;
    const int h  = blockIdx.y;
    const int tid = threadIdx.x;
    const int tx = tid & 15, ty = tid >> 4;

    // ---- Phase 1: q_tile[64][64] = hidden[b, t0:t0+64, :] @ Wq[:, h*64:h*64+64]
    {
        const int ar = tid >> 2, ak = (tid & 3) << 2;
        const int wk = tid >> 4, wc = (tid & 15) << 2;
        const float* Aptr = hidden + ((size_t)b * CHW + t0 + ar) * CHID + ak;
        const float* Wptr = Wq + (size_t)wk * CHID + h * 64 + wc;
        float acc[4][4] = {};
        for (int k0 = 0; k0 < CHID; k0 += 16) {
            const float4 av = *(const float4*)(Aptr + k0);
            S.As[ak + 0][ar] = av.x; S.As[ak + 1][ar] = av.y;
            S.As[ak + 2][ar] = av.z; S.As[ak + 3][ar] = av.w;
            *(float4*)&S.Ws[wk][wc] = *(const float4*)(Wptr + (size_t)k0 * CHID);
            __syncthreads();
#pragma unroll
            for (int kk = 0; kk < 16; kk++) {
                const float a0 = S.As[kk][ty * 4 + 0];
                const float a1 = S.As[kk][ty * 4 + 1];
                const float a2 = S.As[kk][ty * 4 + 2];
                const float a3 = S.As[kk][ty * 4 + 3];
                const float4 b4 = *(const float4*)&S.Ws[kk][tx * 4];
                acc[0][0] += a0 * b4.x; acc[0][1] += a0 * b4.y; acc[0][2] += a0 * b4.z; acc[0][3] += a0 * b4.w;
                acc[1][0] += a1 * b4.x; acc[1][1] += a1 * b4.y; acc[1][2] += a1 * b4.z; acc[1][3] += a1 * b4.w;
                acc[2][0] += a2 * b4.x; acc[2][1] += a2 * b4.y; acc[2][2] += a2 * b4.z; acc[2][3] += a2 * b4.w;
                acc[3][0] += a3 * b4.x; acc[3][1] += a3 * b4.y; acc[3][2] += a3 * b4.z; acc[3][3] += a3 * b4.w;
            }
            __syncthreads();
        }
        const float sc = 0.125f;   // 1/sqrt(64), folded into q => scales both softmaxes
#pragma unroll
        for (int i = 0; i < 4; i++)
#pragma unroll
            for (int j = 0; j < 4; j++)
                S.Qs[ty * 4 + i][tx * 4 + j] = acc[i][j] * sc;
    }

    // ---- Phase 2: stage K/V/KN/VN for (b,h)
    {
        const float* kb  = g_k  + (size_t)b * CLTXT * CHID + h * 64;
        const float* vb  = g_v  + (size_t)b * CLTXT * CHID + h * 64;
        for (int i = tid; i < CLTXT * 64; i += 256) {
            const int j = i >> 6, d = i & 63;
            S.Ks[j][d] = kb[(size_t)j * CHID + d];
            S.Vs[j][d] = vb[(size_t)j * CHID + d];
        }
        const float* knb = g_kn + (size_t)b * CNT * CHID + h * 64;
        const float* vnb = g_vn + (size_t)b * CNT * CHID + h * 64;
        for (int i = tid; i < CNT * 64; i += 256) {
            const int j = i >> 6, d = i & 63;
            S.KNs[j][d] = knb[(size_t)j * CHID + d];
            S.VNs[j][d] = vnb[(size_t)j * CHID + d];
        }
    }
    const int sidx = idx_alter[b];
    __syncthreads();

    // ---- Phase 3: attention, one warp per token (8 warps x 8 tokens)
    const int warp = tid >> 5, lane = tid & 31;
    const int j0 = lane, j1 = lane + 32, j2 = lane + 64;
    const int j2c = (j2 < CLTXT) ? j2 : 0;
    float* wrow = S.Wbuf[warp];
    const float* k0p = S.Ks[j0];
    const float* k1p = S.Ks[j1];
    const float* k2p = S.Ks[j2c];
    const float* knp = S.KNs[lane & 3];

    for (int it = 0; it < 8; ++it) {
        const int t = warp * 8 + it;
        const float* qrow = S.Qs[t];
        float l0 = 0.f, l1 = 0.f, l2 = 0.f, ln = 0.f;
#pragma unroll
        for (int d4 = 0; d4 < 64; d4 += 4) {
            const float4 q  = *(const float4*)(qrow + d4);
            const float4 x  = *(const float4*)(k0p + d4);
            const float4 y  = *(const float4*)(k1p + d4);
            const float4 z  = *(const float4*)(k2p + d4);
            const float4 w4 = *(const float4*)(knp + d4);
            l0 += q.x * x.x + q.y * x.y + q.z * x.z + q.w * x.w;
            l1 += q.x * y.x + q.y * y.y + q.z * y.z + q.w * y.w;
            l2 += q.x * z.x + q.y * z.y + q.z * z.z + q.w * z.w;
            ln += q.x * w4.x + q.y * w4.y + q.z * w4.z + q.w * w4.w;
        }
        if (j2 >= CLTXT) l2 = -1e30f;

        // txt softmax over 77 keys (warp-wide)
        float lm = fmaxf(fmaxf(l0, l1), l2);
#pragma unroll
        for (int o = 16; o; o >>= 1) lm = fmaxf(lm, __shfl_xor_sync(0xffffffffu, lm, o));
        const float e0 = __expf(l0 - lm);
        const float e1 = __expf(l1 - lm);
        const float e2 = (j2 < CLTXT) ? __expf(l2 - lm) : 0.f;
        float es = e0 + e1 + e2;
#pragma unroll
        for (int o = 16; o; o >>= 1) es += __shfl_xor_sync(0xffffffffu, es, o);
        const float inv = 1.f / es;
        wrow[j0] = e0 * inv;
        wrow[j1] = e1 * inv;
        if (j2 < CLTXT) wrow[j2] = e2 * inv;

        // nested softmax over 4 keys (lanes 0..3 authoritative)
        if (lane >= CNT) ln = -1e30f;
        float mn = ln;
        mn = fmaxf(mn, __shfl_xor_sync(0xffffffffu, mn, 1));
        mn = fmaxf(mn, __shfl_xor_sync(0xffffffffu, mn, 2));
        const float en = __expf(ln - mn);
        float sn = en;
        sn += __shfl_xor_sync(0xffffffffu, sn, 1);
        sn += __shfl_xor_sync(0xffffffffu, sn, 2);
        const float wnv = en / sn;
        const float wn0 = __shfl_sync(0xffffffffu, wnv, 0);
        const float wn1 = __shfl_sync(0xffffffffu, wnv, 1);
        const float wn2 = __shfl_sync(0xffffffffu, wnv, 2);
        const float wn3 = __shfl_sync(0xffffffffu, wnv, 3);
        __syncwarp();   // wrow writes visible to whole warp

        // each lane owns dims {2*lane, 2*lane+1}
        const int d0 = lane << 1;
        const float2 a0 = *(const float2*)&S.VNs[0][d0];
        const float2 a1 = *(const float2*)&S.VNs[1][d0];
        const float2 a2 = *(const float2*)&S.VNs[2][d0];
        const float2 a3 = *(const float2*)&S.VNs[3][d0];
        const float vix = wn0 * a0.x + wn1 * a1.x + wn2 * a2.x + wn3 * a3.x;
        const float viy = wn0 * a0.y + wn1 * a1.y + wn2 * a2.y + wn3 * a3.y;

        float bx = 0.f, by = 0.f;
#pragma unroll 7
        for (int j = 0; j < CLTXT; j++) {
            const float wj = wrow[j];
            const float2 vv = *(const float2*)&S.Vs[j][d0];
            bx += wj * vv.x; by += wj * vv.y;
        }
        const float wsel = wrow[sidx];
        const float2 vsel = *(const float2*)&S.Vs[sidx][d0];
        const float ox = bx + wsel * (vix - vsel.x);
        const float oy = by + wsel * (viy - vsel.y);

        float* orow = g_attn + ((size_t)b * CHW + t0 + t) * CHID + h * 64;
        *(float2*)&orow[d0] = make_float2(ox, oy);
        __syncwarp();   // protect wrow against next iteration's writes
    }
}

// ---------------- launch ----------------
extern "C" void kernel_launch(void* const* d_in, const int* in_sizes, int n_in,
                              void* d_out, int out_size)
{
    (void)in_sizes; (void)n_in; (void)out_size;
    const float* hidden = (const float*)d_in[0];
    const float* enc    = (const float*)d_in[1];
    const int*   idx    = (const int*)  d_in[2];
    const float* Wq     = (const float*)d_in[3];
    const float* Wk     = (const float*)d_in[4];
    const float* Wv     = (const float*)d_in[5];
    const float* Wkn    = (const float*)d_in[6];
    const float* Wvn    = (const float*)d_in[7];
    const float* Wout   = (const float*)d_in[8];
    const float* bout   = (const float*)d_in[9];
    float* out = (float*)d_out;

    float *kp, *vp, *knp, *vnp, *ap;
    cudaGetSymbolAddress((void**)&kp,  g_k);
    cudaGetSymbolAddress((void**)&vp,  g_v);
    cudaGetSymbolAddress((void**)&knp, g_kn);
    cudaGetSymbolAddress((void**)&vnp, g_vn);
    cudaGetSymbolAddress((void**)&ap,  g_attn);

    cudaFuncSetAttribute(qattn, cudaFuncAttributeMaxDynamicSharedMemorySize,
                         (int)sizeof(SmemQA));

    // K/V (77 text tokens) and KN/VN (4 img tokens) projections, per batch
    for (int b = 0; b < CB; b++) {
        const float* txt = enc + (size_t)b * CENCL * CCAD;
        const float* img = txt + (size_t)CLTXT * CCAD;
        gemm64<<<dim3(2, CNH), 256>>>(txt, CLTXT, CCAD, CCAD, Wk,  CHID,
                                      kp  + (size_t)b * CLTXT * CHID, CHID, nullptr);
        gemm64<<<dim3(2, CNH), 256>>>(txt, CLTXT, CCAD, CCAD, Wv,  CHID,
                                      vp  + (size_t)b * CLTXT * CHID, CHID, nullptr);
        gemm64<<<dim3(1, CNH), 256>>>(img, CNT,   CCAD, CCAD, Wkn, CHID,
                                      knp + (size_t)b * CNT   * CHID, CHID, nullptr);
        gemm64<<<dim3(1, CNH), 256>>>(img, CNT,   CCAD, CCAD, Wvn, CHID,
                                      vnp + (size_t)b * CNT   * CHID, CHID, nullptr);
    }

    // fused Q projection + nested attention
    qattn<<<dim3(CB * (CHW / 64), CNH), 256, sizeof(SmemQA)>>>(hidden, Wq, idx);

    // output projection + bias
    gemm64<<<dim3((CB * CHW) / 64, CHID / 64), 256>>>(ap, CB * CHW, CHID, CHID,
                                                      Wout, CHID, out, CHID, bout);
}

// round 2
// speedup vs baseline: 1.7733x; 1.7733x over previous
#include <cuda_runtime.h>

#define CB    2
#define CHW   4096
#define CHID  1280
#define CCAD  2048
#define CLTXT 77
#define CNT   4
#define CNH   20
#define CENCL (CLTXT + CNT)   // 81
#define KSLICE 512            // 2048 / 4 splits

// ---------------- scratch (device globals: no allocs allowed) ----------------
__device__ float g_attn[(size_t)CB * CHW * CHID];          // attention output 8192x1280
__device__ float g_proj[(size_t)16 * CB * 80 * CHID];      // [type*4+split][b][row<80][1280]

// =====================================================================
// Projections (K/V/KN/VN, both batches) in ONE launch with split-K.
// grid: x = b*2+rowtile (4), y = 64-col tile (20), z = type*4+split (16)
// =====================================================================
__global__ __launch_bounds__(256) void proj_splitk(
    const float* __restrict__ enc,
    const float* __restrict__ Wk,  const float* __restrict__ Wv,
    const float* __restrict__ Wkn, const float* __restrict__ Wvn)
{
    __shared__ float As[16][68];
    __shared__ float Ws[16][64];
    const int type = blockIdx.z >> 2, split = blockIdx.z & 3;
    const int b = blockIdx.x >> 1, rowtile = blockIdx.x & 1;
    const int M = (type < 2) ? CLTXT : CNT;
    if (rowtile && M <= 64) return;
    const int col0 = blockIdx.y * 64;
    const int row0 = rowtile * 64;
    const float* W = (type == 0) ? Wk : (type == 1) ? Wv : (type == 2) ? Wkn : Wvn;
    const float* A = enc + (size_t)b * CENCL * CCAD + ((type >= 2) ? (size_t)CLTXT * CCAD : 0);
    float* C = g_proj + ((size_t)blockIdx.z * CB + b) * 80 * CHID;

    const int tid = threadIdx.x, tx = tid & 15, ty = tid >> 4;
    const int ar = tid >> 2, ak = (tid & 3) << 2;
    const int wk = tid >> 4, wc = (tid & 15) << 2;
    const bool aok = (row0 + ar) < M;
    const float* Aptr = A + (size_t)(row0 + ar) * CCAD + split * KSLICE + ak;
    const float* Wptr = W + (size_t)(split * KSLICE + wk) * CHID + col0 + wc;

    float acc[4][4] = {};
    for (int k0 = 0; k0 < KSLICE; k0 += 16) {
        float4 av = make_float4(0.f, 0.f, 0.f, 0.f);
        if (aok) av = *(const float4*)(Aptr + k0);
        As[ak + 0][ar] = av.x; As[ak + 1][ar] = av.y;
        As[ak + 2][ar] = av.z; As[ak + 3][ar] = av.w;
        *(float4*)&Ws[wk][wc] = *(const float4*)(Wptr + (size_t)k0 * CHID);
        __syncthreads();
#pragma unroll
        for (int kk = 0; kk < 16; kk++) {
            const float4 a4 = *(const float4*)&As[kk][ty * 4];
            const float4 b4 = *(const float4*)&Ws[kk][tx * 4];
            acc[0][0] += a4.x * b4.x; acc[0][1] += a4.x * b4.y; acc[0][2] += a4.x * b4.z; acc[0][3] += a4.x * b4.w;
            acc[1][0] += a4.y * b4.x; acc[1][1] += a4.y * b4.y; acc[1][2] += a4.y * b4.z; acc[1][3] += a4.y * b4.w;
            acc[2][0] += a4.z * b4.x; acc[2][1] += a4.z * b4.y; acc[2][2] += a4.z * b4.z; acc[2][3] += a4.z * b4.w;
            acc[3][0] += a4.w * b4.x; acc[3][1] += a4.w * b4.y; acc[3][2] += a4.w * b4.z; acc[3][3] += a4.w * b4.w;
        }
        __syncthreads();
    }
#pragma unroll
    for (int i = 0; i < 4; i++) {
        const int r = row0 + ty * 4 + i;
        if (r < M)
            *(float4*)(C + (size_t)r * CHID + col0 + tx * 4) =
                make_float4(acc[i][0], acc[i][1], acc[i][2], acc[i][3]);
    }
}

// =====================================================================
// Fused Q-projection (2 heads per CTA) + nested attention
// =====================================================================
struct Sm2 {
    float As[2][16][68];
    float Ws[2][16][128];
    float Qs[2][64][68];
    float Ks[2][CLTXT][68];
    float Vs[2][CLTXT][68];
    float KNs[2][CNT][68];
    float VNs[2][CNT][68];
    float Wbuf[8][80];
};

// grid: (b*64 + token-tile [128], head-pair [10]), 256 threads
__global__ __launch_bounds__(256, 1) void qattn2(
    const float* __restrict__ hidden,
    const float* __restrict__ Wq,
    const int* __restrict__ idx_alter)
{
    extern __shared__ char raw[];
    Sm2& S = *reinterpret_cast<Sm2*>(raw);
    const int b  = blockIdx.x >> 6;
    const int t0 = (blockIdx.x & 63) << 6;
    const int h0 = blockIdx.y * 2;
    const int tid = threadIdx.x, tx = tid & 15, ty = tid >> 4;

    // ---- Phase 1: Qtile[64][128] = hidden[b, t0:+64, :] @ Wq[:, h0*64 : h0*64+128]
    {
        const int ar = tid >> 2, ak = (tid & 3) << 2;
        const int wk = tid >> 4, wc = (tid & 15) << 2;
        const float* Aptr = hidden + ((size_t)b * CHW + t0 + ar) * CHID + ak;
        const float* Wptr = Wq + (size_t)wk * CHID + h0 * 64;
        float4 an  = *(const float4*)Aptr;
        float4 w0n = *(const float4*)(Wptr + wc);
        float4 w1n = *(const float4*)(Wptr + wc + 64);
        float acc[4][8] = {};
        int buf = 0;
        for (int k0 = 0; k0 < CHID; k0 += 16) {
            S.As[buf][ak + 0][ar] = an.x; S.As[buf][ak + 1][ar] = an.y;
            S.As[buf][ak + 2][ar] = an.z; S.As[buf][ak + 3][ar] = an.w;
            *(float4*)&S.Ws[buf][wk][wc]      = w0n;
            *(float4*)&S.Ws[buf][wk][wc + 64] = w1n;
            __syncthreads();
            if (k0 + 16 < CHID) {
                an  = *(const float4*)(Aptr + k0 + 16);
                w0n = *(const float4*)(Wptr + (size_t)(k0 + 16) * CHID + wc);
                w1n = *(const float4*)(Wptr + (size_t)(k0 + 16) * CHID + wc + 64);
            }
#pragma unroll
            for (int kk = 0; kk < 16; kk++) {
                const float4 a4 = *(const float4*)&S.As[buf][kk][ty * 4];
                const float4 b0 = *(const float4*)&S.Ws[buf][kk][tx * 4];
                const float4 b1 = *(const float4*)&S.Ws[buf][kk][tx * 4 + 64];
                acc[0][0] += a4.x * b0.x; acc[0][1] += a4.x * b0.y; acc[0][2] += a4.x * b0.z; acc[0][3] += a4.x * b0.w;
                acc[1][0] += a4.y * b0.x; acc[1][1] += a4.y * b0.y; acc[1][2] += a4.y * b0.z; acc[1][3] += a4.y * b0.w;
                acc[2][0] += a4.z * b0.x; acc[2][1] += a4.z * b0.y; acc[2][2] += a4.z * b0.z; acc[2][3] += a4.z * b0.w;
                acc[3][0] += a4.w * b0.x; acc[3][1] += a4.w * b0.y; acc[3][2] += a4.w * b0.z; acc[3][3] += a4.w * b0.w;
                acc[0][4] += a4.x * b1.x; acc[0][5] += a4.x * b1.y; acc[0][6] += a4.x * b1.z; acc[0][7] += a4.x * b1.w;
                acc[1][4] += a4.y * b1.x; acc[1][5] += a4.y * b1.y; acc[1][6] += a4.y * b1.z; acc[1][7] += a4.y * b1.w;
                acc[2][4] += a4.z * b1.x; acc[2][5] += a4.z * b1.y; acc[2][6] += a4.z * b1.z; acc[2][7] += a4.z * b1.w;
                acc[3][4] += a4.w * b1.x; acc[3][5] += a4.w * b1.y; acc[3][6] += a4.w * b1.z; acc[3][7] += a4.w * b1.w;
            }
            buf ^= 1;
        }
        const float sc = 0.125f;   // 1/sqrt(64) folded into q
#pragma unroll
        for (int i = 0; i < 4; i++)
#pragma unroll
            for (int j = 0; j < 4; j++) {
                S.Qs[0][ty * 4 + i][tx * 4 + j] = acc[i][j]     * sc;
                S.Qs[1][ty * 4 + i][tx * 4 + j] = acc[i][4 + j] * sc;
            }
    }

    // ---- Phase 2: stage K/V/KN/VN for both heads, summing the 4 split-K partials
#pragma unroll
    for (int hh = 0; hh < 2; hh++) {
        const size_t cb = (size_t)(h0 + hh) * 64;
        for (int i = tid; i < CLTXT * 16; i += 256) {
            const int j = i >> 4, d4 = (i & 15) << 2;
            float4 sk = make_float4(0.f, 0.f, 0.f, 0.f);
            float4 sv = make_float4(0.f, 0.f, 0.f, 0.f);
#pragma unroll
            for (int s = 0; s < 4; s++) {
                const float4 k4 = *(const float4*)(g_proj + ((size_t)(0 * 4 + s) * CB + b) * 80 * CHID + (size_t)j * CHID + cb + d4);
                const float4 v4 = *(const float4*)(g_proj + ((size_t)(1 * 4 + s) * CB + b) * 80 * CHID + (size_t)j * CHID + cb + d4);
                sk.x += k4.x; sk.y += k4.y; sk.z += k4.z; sk.w += k4.w;
                sv.x += v4.x; sv.y += v4.y; sv.z += v4.z; sv.w += v4.w;
            }
            *(float4*)&S.Ks[hh][j][d4] = sk;
            *(float4*)&S.Vs[hh][j][d4] = sv;
        }
        for (int i = tid; i < CNT * 16; i += 256) {
            const int j = i >> 4, d4 = (i & 15) << 2;
            float4 sk = make_float4(0.f, 0.f, 0.f, 0.f);
            float4 sv = make_float4(0.f, 0.f, 0.f, 0.f);
#pragma unroll
            for (int s = 0; s < 4; s++) {
                const float4 k4 = *(const float4*)(g_proj + ((size_t)(2 * 4 + s) * CB + b) * 80 * CHID + (size_t)j * CHID + cb + d4);
                const float4 v4 = *(const float4*)(g_proj + ((size_t)(3 * 4 + s) * CB + b) * 80 * CHID + (size_t)j * CHID + cb + d4);
                sk.x += k4.x; sk.y += k4.y; sk.z += k4.z; sk.w += k4.w;
                sv.x += v4.x; sv.y += v4.y; sv.z += v4.z; sv.w += v4.w;
            }
            *(float4*)&S.KNs[hh][j][d4] = sk;
            *(float4*)&S.VNs[hh][j][d4] = sv;
        }
    }
    const int sidx = idx_alter[b];
    __syncthreads();

    // ---- Phase 3: attention, one warp per token (8 warps x 8 tokens), per head
    const int warp = tid >> 5, lane = tid & 31;
    const int j0 = lane, j1 = lane + 32, j2 = lane + 64;
    const int j2c = (j2 < CLTXT) ? j2 : 0;
    float* wrow = S.Wbuf[warp];

#pragma unroll
    for (int hh = 0; hh < 2; hh++) {
        const float* k0p = S.Ks[hh][j0];
        const float* k1p = S.Ks[hh][j1];
        const float* k2p = S.Ks[hh][j2c];
        const float* knp = S.KNs[hh][lane & 3];

        for (int it = 0; it < 8; ++it) {
            const int t = warp * 8 + it;
            const float* qrow = S.Qs[hh][t];
            float l0 = 0.f, l1 = 0.f, l2 = 0.f, ln = 0.f;
#pragma unroll
            for (int d4 = 0; d4 < 64; d4 += 4) {
                const float4 q  = *(const float4*)(qrow + d4);
                const float4 x  = *(const float4*)(k0p + d4);
                const float4 y  = *(const float4*)(k1p + d4);
                const float4 z  = *(const float4*)(k2p + d4);
                const float4 w4 = *(const float4*)(knp + d4);
                l0 += q.x * x.x + q.y * x.y + q.z * x.z + q.w * x.w;
                l1 += q.x * y.x + q.y * y.y + q.z * y.z + q.w * y.w;
                l2 += q.x * z.x + q.y * z.y + q.z * z.z + q.w * z.w;
                ln += q.x * w4.x + q.y * w4.y + q.z * w4.z + q.w * w4.w;
            }
            if (j2 >= CLTXT) l2 = -1e30f;

            // txt softmax over 77 keys (warp-wide)
            float lm = fmaxf(fmaxf(l0, l1), l2);
#pragma unroll
            for (int o = 16; o; o >>= 1) lm = fmaxf(lm, __shfl_xor_sync(0xffffffffu, lm, o));
            const float e0 = __expf(l0 - lm);
            const float e1 = __expf(l1 - lm);
            const float e2 = (j2 < CLTXT) ? __expf(l2 - lm) : 0.f;
            float es = e0 + e1 + e2;
#pragma unroll
            for (int o = 16; o; o >>= 1) es += __shfl_xor_sync(0xffffffffu, es, o);
            const float inv = 1.f / es;
            wrow[j0] = e0 * inv;
            wrow[j1] = e1 * inv;
            if (j2 < CLTXT) wrow[j2] = e2 * inv;

            // nested softmax over 4 keys
            if (lane >= CNT) ln = -1e30f;
            float mn = ln;
            mn = fmaxf(mn, __shfl_xor_sync(0xffffffffu, mn, 1));
            mn = fmaxf(mn, __shfl_xor_sync(0xffffffffu, mn, 2));
            const float en = __expf(ln - mn);
            float sn = en;
            sn += __shfl_xor_sync(0xffffffffu, sn, 1);
            sn += __shfl_xor_sync(0xffffffffu, sn, 2);
            const float wnv = en / sn;
            const float wn0 = __shfl_sync(0xffffffffu, wnv, 0);
            const float wn1 = __shfl_sync(0xffffffffu, wnv, 1);
            const float wn2 = __shfl_sync(0xffffffffu, wnv, 2);
            const float wn3 = __shfl_sync(0xffffffffu, wnv, 3);
            __syncwarp();   // wrow visible warp-wide

            const int d0 = lane << 1;
            const float2 a0 = *(const float2*)&S.VNs[hh][0][d0];
            const float2 a1 = *(const float2*)&S.VNs[hh][1][d0];
            const float2 a2 = *(const float2*)&S.VNs[hh][2][d0];
            const float2 a3 = *(const float2*)&S.VNs[hh][3][d0];
            const float vix = wn0 * a0.x + wn1 * a1.x + wn2 * a2.x + wn3 * a3.x;
            const float viy = wn0 * a0.y + wn1 * a1.y + wn2 * a2.y + wn3 * a3.y;

            float bx = 0.f, by = 0.f;
#pragma unroll 7
            for (int j = 0; j < CLTXT; j++) {
                const float wj = wrow[j];
                const float2 vv = *(const float2*)&S.Vs[hh][j][d0];
                bx += wj * vv.x; by += wj * vv.y;
            }
            const float wsel = wrow[sidx];
            const float2 vsel = *(const float2*)&S.Vs[hh][sidx][d0];
            const float ox = bx + wsel * (vix - vsel.x);
            const float oy = by + wsel * (viy - vsel.y);

            float* orow = g_attn + ((size_t)b * CHW + t0 + t) * CHID + (h0 + hh) * 64;
            *(float2*)&orow[d0] = make_float2(ox, oy);
            __syncwarp();   // protect wrow against next iteration's writes
        }
    }
}

// =====================================================================
// Output projection: out = g_attn @ Wout + bias  (8192x1280x1280)
// tile 64x128, thread 4x8, double-buffered. grid (128, 10)
// =====================================================================
__global__ __launch_bounds__(256) void gemm_out(
    const float* __restrict__ A, const float* __restrict__ W,
    const float* __restrict__ bias, float* __restrict__ C)
{
    __shared__ float As[2][16][68];
    __shared__ float Ws[2][16][128];
    const int row0 = blockIdx.x * 64;
    const int col0 = blockIdx.y * 128;
    const int tid = threadIdx.x, tx = tid & 15, ty = tid >> 4;
    const int ar = tid >> 2, ak = (tid & 3) << 2;
    const int wk = tid >> 4, wc = (tid & 15) << 2;
    const float* Aptr = A + (size_t)(row0 + ar) * CHID + ak;
    const float* Wptr = W + (size_t)wk * CHID + col0;

    float4 an  = *(const float4*)Aptr;
    float4 w0n = *(const float4*)(Wptr + wc);
    float4 w1n = *(const float4*)(Wptr + wc + 64);
    float acc[4][8] = {};
    int buf = 0;
    for (int k0 = 0; k0 < CHID; k0 += 16) {
        As[buf][ak + 0][ar] = an.x; As[buf][ak + 1][ar] = an.y;
        As[buf][ak + 2][ar] = an.z; As[buf][ak + 3][ar] = an.w;
        *(float4*)&Ws[buf][wk][wc]      = w0n;
        *(float4*)&Ws[buf][wk][wc + 64] = w1n;
        __syncthreads();
        if (k0 + 16 < CHID) {
            an  = *(const float4*)(Aptr + k0 + 16);
            w0n = *(const float4*)(Wptr + (size_t)(k0 + 16) * CHID + wc);
            w1n = *(const float4*)(Wptr + (size_t)(k0 + 16) * CHID + wc + 64);
        }
#pragma unroll
        for (int kk = 0; kk < 16; kk++) {
            const float4 a4 = *(const float4*)&As[buf][kk][ty * 4];
            const float4 b0 = *(const float4*)&Ws[buf][kk][tx * 4];
            const float4 b1 = *(const float4*)&Ws[buf][kk][tx * 4 + 64];
            acc[0][0] += a4.x * b0.x; acc[0][1] += a4.x * b0.y; acc[0][2] += a4.x * b0.z; acc[0][3] += a4.x * b0.w;
            acc[1][0] += a4.y * b0.x; acc[1][1] += a4.y * b0.y; acc[1][2] += a4.y * b0.z; acc[1][3] += a4.y * b0.w;
            acc[2][0] += a4.z * b0.x; acc[2][1] += a4.z * b0.y; acc[2][2] += a4.z * b0.z; acc[2][3] += a4.z * b0.w;
            acc[3][0] += a4.w * b0.x; acc[3][1] += a4.w * b0.y; acc[3][2] += a4.w * b0.z; acc[3][3] += a4.w * b0.w;
            acc[0][4] += a4.x * b1.x; acc[0][5] += a4.x * b1.y; acc[0][6] += a4.x * b1.z; acc[0][7] += a4.x * b1.w;
            acc[1][4] += a4.y * b1.x; acc[1][5] += a4.y * b1.y; acc[1][6] += a4.y * b1.z; acc[1][7] += a4.y * b1.w;
            acc[2][4] += a4.z * b1.x; acc[2][5] += a4.z * b1.y; acc[2][6] += a4.z * b1.z; acc[2][7] += a4.z * b1.w;
            acc[3][4] += a4.w * b1.x; acc[3][5] += a4.w * b1.y; acc[3][6] += a4.w * b1.z; acc[3][7] += a4.w * b1.w;
        }
        buf ^= 1;
    }

    const float4 bv0 = *(const float4*)(bias + col0 + tx * 4);
    const float4 bv1 = *(const float4*)(bias + col0 + tx * 4 + 64);
#pragma unroll
    for (int i = 0; i < 4; i++) {
        const int r = row0 + ty * 4 + i;
        *(float4*)(C + (size_t)r * CHID + col0 + tx * 4) =
            make_float4(acc[i][0] + bv0.x, acc[i][1] + bv0.y, acc[i][2] + bv0.z, acc[i][3] + bv0.w);
        *(float4*)(C + (size_t)r * CHID + col0 + tx * 4 + 64) =
            make_float4(acc[i][4] + bv1.x, acc[i][5] + bv1.y, acc[i][6] + bv1.z, acc[i][7] + bv1.w);
    }
}

// ---------------- launch ----------------
extern "C" void kernel_launch(void* const* d_in, const int* in_sizes, int n_in,
                              void* d_out, int out_size)
{
    (void)in_sizes; (void)n_in; (void)out_size;
    const float* hidden = (const float*)d_in[0];
    const float* enc    = (const float*)d_in[1];
    const int*   idx    = (const int*)  d_in[2];
    const float* Wq     = (const float*)d_in[3];
    const float* Wk     = (const float*)d_in[4];
    const float* Wv     = (const float*)d_in[5];
    const float* Wkn    = (const float*)d_in[6];
    const float* Wvn    = (const float*)d_in[7];
    const float* Wout   = (const float*)d_in[8];
    const float* bout   = (const float*)d_in[9];
    float* out = (float*)d_out;

    float* ap;
    cudaGetSymbolAddress((void**)&ap, g_attn);

    cudaFuncSetAttribute(qattn2, cudaFuncAttributeMaxDynamicSharedMemorySize,
                         (int)sizeof(Sm2));

    // all projections, one launch, split-K over 2048
    proj_splitk<<<dim3(4, CNH, 16), 256>>>(enc, Wk, Wv, Wkn, Wvn);

    // fused Q projection (2 heads/CTA) + nested attention
    qattn2<<<dim3(CB * (CHW / 64), CNH / 2), 256, sizeof(Sm2)>>>(hidden, Wq, idx);

    // output projection + bias
    gemm_out<<<dim3((CB * CHW) / 64, CHID / 128), 256>>>(ap, Wout, bout, out);
}

// round 3
// speedup vs baseline: 2.7848x; 1.5704x over previous
#include <cuda_runtime.h>
#include <cuda_bf16.h>
#include <cstdint>

#define CB    2
#define CHW   4096
#define CHID  1280
#define CCAD  2048
#define CLTXT 77
#define CNT   4
#define CNH   20
#define CENCL (CLTXT + CNT)   // 81
#define KSLICE 512

#define GM 8192               // CB*CHW
#define GK 1280
#define GN 1280

// ---------------- scratch (device globals: no allocs allowed) ----------------
__device__ float g_q[(size_t)GM * GK];                     // Q = hidden@Wq (fp32)
__device__ float g_proj[(size_t)16 * CB * 80 * CHID];      // split-K partials K/V/KN/VN
__device__ __nv_bfloat16 g_hid_h[(size_t)GM * GK];
__device__ __nv_bfloat16 g_hid_l[(size_t)GM * GK];
__device__ __nv_bfloat16 g_wq_h[(size_t)GK * GN];
__device__ __nv_bfloat16 g_wq_l[(size_t)GK * GN];
__device__ __nv_bfloat16 g_wo_h[(size_t)GK * GN];
__device__ __nv_bfloat16 g_wo_l[(size_t)GK * GN];
__device__ __nv_bfloat16 g_attn_h[(size_t)GM * GK];
__device__ __nv_bfloat16 g_attn_l[(size_t)GM * GK];

// =====================================================================
// fp32 -> (hi, lo) bf16 split
// =====================================================================
__global__ __launch_bounds__(512) void splitf(
    const float* __restrict__ x,
    __nv_bfloat16* __restrict__ hi, __nv_bfloat16* __restrict__ lo, int n)
{
    for (int i = (blockIdx.x * 512 + threadIdx.x) * 4; i < n; i += gridDim.x * 512 * 4) {
        const float4 v = *(const float4*)(x + i);
        __nv_bfloat16 h0 = __float2bfloat16(v.x);
        __nv_bfloat16 h1 = __float2bfloat16(v.y);
        __nv_bfloat16 h2 = __float2bfloat16(v.z);
        __nv_bfloat16 h3 = __float2bfloat16(v.w);
        __nv_bfloat16 l0 = __float2bfloat16(v.x - __bfloat162float(h0));
        __nv_bfloat16 l1 = __float2bfloat16(v.y - __bfloat162float(h1));
        __nv_bfloat16 l2 = __float2bfloat16(v.z - __bfloat162float(h2));
        __nv_bfloat16 l3 = __float2bfloat16(v.w - __bfloat162float(h3));
        *(__nv_bfloat162*)(hi + i)     = __nv_bfloat162(h0, h1);
        *(__nv_bfloat162*)(hi + i + 2) = __nv_bfloat162(h2, h3);
        *(__nv_bfloat162*)(lo + i)     = __nv_bfloat162(l0, l1);
        *(__nv_bfloat162*)(lo + i + 2) = __nv_bfloat162(l2, l3);
    }
}

// =====================================================================
// bf16x3 tensor-core GEMM: C[GM,GN] = A@B (+bias), fp32 accum
// CTA 128x128, 512 thr (16 warps 4x4), warp tile 32x32, BK=32, cp.async 2-stage
// =====================================================================
#define CP_ASYNC(dst, src) asm volatile("cp.async.cg.shared.global [%0], [%1], 16;" :: "r"(dst), "l"(src))

__device__ __forceinline__ void ldsm4(uint32_t* r, uint32_t a) {
    asm volatile("ldmatrix.sync.aligned.m8n8.x4.shared.b16 {%0,%1,%2,%3}, [%4];"
        : "=r"(r[0]), "=r"(r[1]), "=r"(r[2]), "=r"(r[3]) : "r"(a));
}
__device__ __forceinline__ void ldsm4t(uint32_t* r, uint32_t a) {
    asm volatile("ldmatrix.sync.aligned.m8n8.x4.trans.shared.b16 {%0,%1,%2,%3}, [%4];"
        : "=r"(r[0]), "=r"(r[1]), "=r"(r[2]), "=r"(r[3]) : "r"(a));
}
__device__ __forceinline__ void mma16816(float* c, const uint32_t* a, const uint32_t* b) {
    asm volatile("mma.sync.aligned.m16n8k16.row.col.f32.bf16.bf16.f32 "
        "{%0,%1,%2,%3}, {%4,%5,%6,%7}, {%8,%9}, {%0,%1,%2,%3};"
        : "+f"(c[0]), "+f"(c[1]), "+f"(c[2]), "+f"(c[3])
        : "r"(a[0]), "r"(a[1]), "r"(a[2]), "r"(a[3]), "r"(b[0]), "r"(b[1]));
}

#define A_PITCH 40
#define B_PITCH 136
#define ABUF (128 * A_PITCH)   // elems
#define BBUF (32 * B_PITCH)

__global__ __launch_bounds__(512, 1) void gemm_bf3(
    const __nv_bfloat16* __restrict__ Ahi, const __nv_bfloat16* __restrict__ Alo,
    const __nv_bfloat16* __restrict__ Bhi, const __nv_bfloat16* __restrict__ Blo,
    const float* __restrict__ bias, float* __restrict__ C)
{
    extern __shared__ __align__(16) char sm[];
    __nv_bfloat16* sAh = (__nv_bfloat16*)sm;       // [2][ABUF]
    __nv_bfloat16* sAl = sAh + 2 * ABUF;
    __nv_bfloat16* sBh = sAl + 2 * ABUF;           // [2][BBUF]
    __nv_bfloat16* sBl = sBh + 2 * BBUF;

    const int tid = threadIdx.x;
    const int m0 = blockIdx.x * 128, n0 = blockIdx.y * 128;
    const int lane = tid & 31, warp = tid >> 5;
    const int wm = warp >> 2, wn = warp & 3;

    // gmem staging (cp.async 16B per array per thread per 32-k tile)
    const int arow = tid >> 2, ak8 = (tid & 3) << 3;
    const int brow = tid >> 4, bn8 = (tid & 15) << 3;
    const __nv_bfloat16* gAh = Ahi + (size_t)(m0 + arow) * GK + ak8;
    const __nv_bfloat16* gAl = Alo + (size_t)(m0 + arow) * GK + ak8;
    const __nv_bfloat16* gBh = Bhi + (size_t)brow * GN + n0 + bn8;
    const __nv_bfloat16* gBl = Blo + (size_t)brow * GN + n0 + bn8;
    const uint32_t dAh = (uint32_t)__cvta_generic_to_shared(sAh) + (uint32_t)(arow * A_PITCH + ak8) * 2;
    const uint32_t dAl = (uint32_t)__cvta_generic_to_shared(sAl) + (uint32_t)(arow * A_PITCH + ak8) * 2;
    const uint32_t dBh = (uint32_t)__cvta_generic_to_shared(sBh) + (uint32_t)(brow * B_PITCH + bn8) * 2;
    const uint32_t dBl = (uint32_t)__cvta_generic_to_shared(sBl) + (uint32_t)(brow * B_PITCH + bn8) * 2;

    // prologue: buffer 0
    CP_ASYNC(dAh, gAh); CP_ASYNC(dAl, gAl); CP_ASYNC(dBh, gBh); CP_ASYNC(dBl, gBl);
    asm volatile("cp.async.commit_group;");
    gAh += 32; gAl += 32; gBh += (size_t)32 * GN; gBl += (size_t)32 * GN;

    float acc[2][4][4] = {};

    // ldmatrix per-lane base addrs (buffer 0)
    const uint32_t aOff = (uint32_t)((wm * 32 + (lane & 15)) * A_PITCH + ((lane >> 4) << 3)) * 2;
    const uint32_t aBh0 = (uint32_t)__cvta_generic_to_shared(sAh) + aOff;
    const uint32_t aBl0 = (uint32_t)__cvta_generic_to_shared(sAl) + aOff;
    const uint32_t bOff = (uint32_t)(((lane & 7) + ((lane >> 3) & 1) * 8) * B_PITCH
                                     + wn * 32 + ((lane >> 4) << 3)) * 2;
    const uint32_t bBh0 = (uint32_t)__cvta_generic_to_shared(sBh) + bOff;
    const uint32_t bBl0 = (uint32_t)__cvta_generic_to_shared(sBl) + bOff;

    const int NKT = GK / 32;   // 40
    for (int kt = 0; kt < NKT; kt++) {
        const int buf = kt & 1;
        if (kt < NKT - 1) {
            const uint32_t ao = (uint32_t)(buf ^ 1) * (ABUF * 2);
            const uint32_t bo = (uint32_t)(buf ^ 1) * (BBUF * 2);
            CP_ASYNC(dAh + ao, gAh); CP_ASYNC(dAl + ao, gAl);
            CP_ASYNC(dBh + bo, gBh); CP_ASYNC(dBl + bo, gBl);
            asm volatile("cp.async.commit_group;");
            gAh += 32; gAl += 32; gBh += (size_t)32 * GN; gBl += (size_t)32 * GN;
            asm volatile("cp.async.wait_group 1;");
        } else {
            asm volatile("cp.async.wait_group 0;");
        }
        __syncthreads();

        const uint32_t ah = aBh0 + buf * (ABUF * 2);
        const uint32_t al = aBl0 + buf * (ABUF * 2);
        const uint32_t bh = bBh0 + buf * (BBUF * 2);
        const uint32_t bl = bBl0 + buf * (BBUF * 2);
#pragma unroll
        for (int ks = 0; ks < 2; ks++) {
            const uint32_t ka  = ah + ks * 32;               // +16 k elems = 32B
            const uint32_t kal = al + ks * 32;
            const uint32_t kb  = bh + ks * (16 * B_PITCH * 2);
            const uint32_t kbl = bl + ks * (16 * B_PITCH * 2);
            uint32_t Ah0[4], Ah1[4], Al0[4], Al1[4];
            ldsm4(Ah0, ka);
            ldsm4(Ah1, ka + 16 * A_PITCH * 2);
            ldsm4(Al0, kal);
            ldsm4(Al1, kal + 16 * A_PITCH * 2);
            uint32_t Bh[8], Bl[8];
            ldsm4t(Bh,     kb);          // n-frags 0,1
            ldsm4t(Bh + 4, kb + 32);     // n-frags 2,3 (+16 cols = 32B)
            ldsm4t(Bl,     kbl);
            ldsm4t(Bl + 4, kbl + 32);
#pragma unroll
            for (int j = 0; j < 4; j++) {
                const uint32_t* bhj = &Bh[j * 2];
                const uint32_t* blj = &Bl[j * 2];
                mma16816(acc[0][j], Ah0, bhj);
                mma16816(acc[0][j], Ah0, blj);
                mma16816(acc[0][j], Al0, bhj);
                mma16816(acc[1][j], Ah1, bhj);
                mma16816(acc[1][j], Ah1, blj);
                mma16816(acc[1][j], Al1, bhj);
            }
        }
        __syncthreads();
    }

    // epilogue
#pragma unroll
    for (int fm = 0; fm < 2; fm++) {
        const int r0 = m0 + wm * 32 + fm * 16 + (lane >> 2);
#pragma unroll
        for (int j = 0; j < 4; j++) {
            const int cc = n0 + wn * 32 + j * 8 + ((lane & 3) << 1);
            float b0 = 0.f, b1 = 0.f;
            if (bias) { b0 = bias[cc]; b1 = bias[cc + 1]; }
            *(float2*)(C + (size_t)r0 * GN + cc) =
                make_float2(acc[fm][j][0] + b0, acc[fm][j][1] + b1);
            *(float2*)(C + (size_t)(r0 + 8) * GN + cc) =
                make_float2(acc[fm][j][2] + b0, acc[fm][j][3] + b1);
        }
    }
}

// =====================================================================
// Projections (K/V/KN/VN, both batches), split-K fp32 (unchanged)
// =====================================================================
__global__ __launch_bounds__(256) void proj_splitk(
    const float* __restrict__ enc,
    const float* __restrict__ Wk,  const float* __restrict__ Wv,
    const float* __restrict__ Wkn, const float* __restrict__ Wvn)
{
    __shared__ float As[16][68];
    __shared__ float Ws[16][64];
    const int type = blockIdx.z >> 2, split = blockIdx.z & 3;
    const int b = blockIdx.x >> 1, rowtile = blockIdx.x & 1;
    const int M = (type < 2) ? CLTXT : CNT;
    if (rowtile && M <= 64) return;
    const int col0 = blockIdx.y * 64;
    const int row0 = rowtile * 64;
    const float* W = (type == 0) ? Wk : (type == 1) ? Wv : (type == 2) ? Wkn : Wvn;
    const float* A = enc + (size_t)b * CENCL * CCAD + ((type >= 2) ? (size_t)CLTXT * CCAD : 0);
    float* C = g_proj + ((size_t)blockIdx.z * CB + b) * 80 * CHID;

    const int tid = threadIdx.x, tx = tid & 15, ty = tid >> 4;
    const int ar = tid >> 2, ak = (tid & 3) << 2;
    const int wk = tid >> 4, wc = (tid & 15) << 2;
    const bool aok = (row0 + ar) < M;
    const float* Aptr = A + (size_t)(row0 + ar) * CCAD + split * KSLICE + ak;
    const float* Wptr = W + (size_t)(split * KSLICE + wk) * CHID + col0 + wc;

    float acc[4][4] = {};
    for (int k0 = 0; k0 < KSLICE; k0 += 16) {
        float4 av = make_float4(0.f, 0.f, 0.f, 0.f);
        if (aok) av = *(const float4*)(Aptr + k0);
        As[ak + 0][ar] = av.x; As[ak + 1][ar] = av.y;
        As[ak + 2][ar] = av.z; As[ak + 3][ar] = av.w;
        *(float4*)&Ws[wk][wc] = *(const float4*)(Wptr + (size_t)k0 * CHID);
        __syncthreads();
#pragma unroll
        for (int kk = 0; kk < 16; kk++) {
            const float4 a4 = *(const float4*)&As[kk][ty * 4];
            const float4 b4 = *(const float4*)&Ws[kk][tx * 4];
            acc[0][0] += a4.x * b4.x; acc[0][1] += a4.x * b4.y; acc[0][2] += a4.x * b4.z; acc[0][3] += a4.x * b4.w;
            acc[1][0] += a4.y * b4.x; acc[1][1] += a4.y * b4.y; acc[1][2] += a4.y * b4.z; acc[1][3] += a4.y * b4.w;
            acc[2][0] += a4.z * b4.x; acc[2][1] += a4.z * b4.y; acc[2][2] += a4.z * b4.z; acc[2][3] += a4.z * b4.w;
            acc[3][0] += a4.w * b4.x; acc[3][1] += a4.w * b4.y; acc[3][2] += a4.w * b4.z; acc[3][3] += a4.w * b4.w;
        }
        __syncthreads();
    }
#pragma unroll
    for (int i = 0; i < 4; i++) {
        const int r = row0 + ty * 4 + i;
        if (r < M)
            *(float4*)(C + (size_t)r * CHID + col0 + tx * 4) =
                make_float4(acc[i][0], acc[i][1], acc[i][2], acc[i][3]);
    }
}

// =====================================================================
// Attention (Q from gmem), 2 heads/CTA; output written as bf16 hi/lo split
// =====================================================================
struct SmA {
    float Qs[2][64][68];
    float Ks[2][CLTXT][68];
    float Vs[2][CLTXT][68];
    float KNs[2][CNT][68];
    float VNs[2][CNT][68];
    float Wbuf[8][80];
};

__global__ __launch_bounds__(256, 1) void qattn_lite(const int* __restrict__ idx_alter)
{
    extern __shared__ char raw[];
    SmA& S = *reinterpret_cast<SmA*>(raw);
    const int b  = blockIdx.x >> 6;
    const int t0 = (blockIdx.x & 63) << 6;
    const int h0 = blockIdx.y * 2;
    const int tid = threadIdx.x;

    // stage Q (scaled) : 64 tokens x 128 cols
    for (int i = tid; i < 64 * 32; i += 256) {
        const int t = i >> 5, c4 = (i & 31) << 2;
        const int hh = c4 >> 6, d = c4 & 63;
        float4 q = *(const float4*)(g_q + ((size_t)b * CHW + t0 + t) * CHID + h0 * 64 + c4);
        q.x *= 0.125f; q.y *= 0.125f; q.z *= 0.125f; q.w *= 0.125f;
        *(float4*)&S.Qs[hh][t][d] = q;
    }

    // stage K/V/KN/VN (sum the 4 split-K partials)
#pragma unroll
    for (int hh = 0; hh < 2; hh++) {
        const size_t cb = (size_t)(h0 + hh) * 64;
        for (int i = tid; i < CLTXT * 16; i += 256) {
            const int j = i >> 4, d4 = (i & 15) << 2;
            float4 sk = make_float4(0.f, 0.f, 0.f, 0.f);
            float4 sv = make_float4(0.f, 0.f, 0.f, 0.f);
#pragma unroll
            for (int s = 0; s < 4; s++) {
                const float4 k4 = *(const float4*)(g_proj + ((size_t)(0 + s) * CB + b) * 80 * CHID + (size_t)j * CHID + cb + d4);
                const float4 v4 = *(const float4*)(g_proj + ((size_t)(4 + s) * CB + b) * 80 * CHID + (size_t)j * CHID + cb + d4);
                sk.x += k4.x; sk.y += k4.y; sk.z += k4.z; sk.w += k4.w;
                sv.x += v4.x; sv.y += v4.y; sv.z += v4.z; sv.w += v4.w;
            }
            *(float4*)&S.Ks[hh][j][d4] = sk;
            *(float4*)&S.Vs[hh][j][d4] = sv;
        }
        for (int i = tid; i < CNT * 16; i += 256) {
            const int j = i >> 4, d4 = (i & 15) << 2;
            float4 sk = make_float4(0.f, 0.f, 0.f, 0.f);
            float4 sv = make_float4(0.f, 0.f, 0.f, 0.f);
#pragma unroll
            for (int s = 0; s < 4; s++) {
                const float4 k4 = *(const float4*)(g_proj + ((size_t)(8  + s) * CB + b) * 80 * CHID + (size_t)j * CHID + cb + d4);
                const float4 v4 = *(const float4*)(g_proj + ((size_t)(12 + s) * CB + b) * 80 * CHID + (size_t)j * CHID + cb + d4);
                sk.x += k4.x; sk.y += k4.y; sk.z += k4.z; sk.w += k4.w;
                sv.x += v4.x; sv.y += v4.y; sv.z += v4.z; sv.w += v4.w;
            }
            *(float4*)&S.KNs[hh][j][d4] = sk;
            *(float4*)&S.VNs[hh][j][d4] = sv;
        }
    }
    const int sidx = idx_alter[b];
    __syncthreads();

    const int warp = tid >> 5, lane = tid & 31;
    const int j0 = lane, j1 = lane + 32, j2 = lane + 64;
    const int j2c = (j2 < CLTXT) ? j2 : 0;
    float* wrow = S.Wbuf[warp];

#pragma unroll
    for (int hh = 0; hh < 2; hh++) {
        const float* k0p = S.Ks[hh][j0];
        const float* k1p = S.Ks[hh][j1];
        const float* k2p = S.Ks[hh][j2c];
        const float* knp = S.KNs[hh][lane & 3];

        for (int it = 0; it < 8; ++it) {
            const int t = warp * 8 + it;
            const float* qrow = S.Qs[hh][t];
            float l0 = 0.f, l1 = 0.f, l2 = 0.f, ln = 0.f;
#pragma unroll
            for (int d4 = 0; d4 < 64; d4 += 4) {
                const float4 q  = *(const float4*)(qrow + d4);
                const float4 x  = *(const float4*)(k0p + d4);
                const float4 y  = *(const float4*)(k1p + d4);
                const float4 z  = *(const float4*)(k2p + d4);
                const float4 w4 = *(const float4*)(knp + d4);
                l0 += q.x * x.x + q.y * x.y + q.z * x.z + q.w * x.w;
                l1 += q.x * y.x + q.y * y.y + q.z * y.z + q.w * y.w;
                l2 += q.x * z.x + q.y * z.y + q.z * z.z + q.w * z.w;
                ln += q.x * w4.x + q.y * w4.y + q.z * w4.z + q.w * w4.w;
            }
            if (j2 >= CLTXT) l2 = -1e30f;

            float lm = fmaxf(fmaxf(l0, l1), l2);
#pragma unroll
            for (int o = 16; o; o >>= 1) lm = fmaxf(lm, __shfl_xor_sync(0xffffffffu, lm, o));
            const float e0 = __expf(l0 - lm);
            const float e1 = __expf(l1 - lm);
            const float e2 = (j2 < CLTXT) ? __expf(l2 - lm) : 0.f;
            float es = e0 + e1 + e2;
#pragma unroll
            for (int o = 16; o; o >>= 1) es += __shfl_xor_sync(0xffffffffu, es, o);
            const float inv = 1.f / es;
            wrow[j0] = e0 * inv;
            wrow[j1] = e1 * inv;
            if (j2 < CLTXT) wrow[j2] = e2 * inv;

            if (lane >= CNT) ln = -1e30f;
            float mn = ln;
            mn = fmaxf(mn, __shfl_xor_sync(0xffffffffu, mn, 1));
            mn = fmaxf(mn, __shfl_xor_sync(0xffffffffu, mn, 2));
            const float en = __expf(ln - mn);
            float sn = en;
            sn += __shfl_xor_sync(0xffffffffu, sn, 1);
            sn += __shfl_xor_sync(0xffffffffu, sn, 2);
            const float wnv = en / sn;
            const float wn0 = __shfl_sync(0xffffffffu, wnv, 0);
            const float wn1 = __shfl_sync(0xffffffffu, wnv, 1);
            const float wn2 = __shfl_sync(0xffffffffu, wnv, 2);
            const float wn3 = __shfl_sync(0xffffffffu, wnv, 3);
            __syncwarp();

            const int d0 = lane << 1;
            const float2 a0 = *(const float2*)&S.VNs[hh][0][d0];
            const float2 a1 = *(const float2*)&S.VNs[hh][1][d0];
            const float2 a2 = *(const float2*)&S.VNs[hh][2][d0];
            const float2 a3 = *(const float2*)&S.VNs[hh][3][d0];
            const float vix = wn0 * a0.x + wn1 * a1.x + wn2 * a2.x + wn3 * a3.x;
            const float viy = wn0 * a0.y + wn1 * a1.y + wn2 * a2.y + wn3 * a3.y;

            float bx = 0.f, by = 0.f;
#pragma unroll 7
            for (int j = 0; j < CLTXT; j++) {
                const float wj = wrow[j];
                const float2 vv = *(const float2*)&S.Vs[hh][j][d0];
                bx += wj * vv.x; by += wj * vv.y;
            }
            const float wsel = wrow[sidx];
            const float2 vsel = *(const float2*)&S.Vs[hh][sidx][d0];
            const float ox = bx + wsel * (vix - vsel.x);
            const float oy = by + wsel * (viy - vsel.y);

            // write bf16 hi/lo split directly
            const size_t off = ((size_t)b * CHW + t0 + t) * CHID + (h0 + hh) * 64 + d0;
            const __nv_bfloat16 hx = __float2bfloat16(ox);
            const __nv_bfloat16 hy = __float2bfloat16(oy);
            const __nv_bfloat16 lx = __float2bfloat16(ox - __bfloat162float(hx));
            const __nv_bfloat16 ly = __float2bfloat16(oy - __bfloat162float(hy));
            *(__nv_bfloat162*)(g_attn_h + off) = __nv_bfloat162(hx, hy);
            *(__nv_bfloat162*)(g_attn_l + off) = __nv_bfloat162(lx, ly);
            __syncwarp();
        }
    }
}

// ---------------- launch ----------------
extern "C" void kernel_launch(void* const* d_in, const int* in_sizes, int n_in,
                              void* d_out, int out_size)
{
    (void)in_sizes; (void)n_in; (void)out_size;
    const float* hidden = (const float*)d_in[0];
    const float* enc    = (const float*)d_in[1];
    const int*   idx    = (const int*)  d_in[2];
    const float* Wq     = (const float*)d_in[3];
    const float* Wk     = (const float*)d_in[4];
    const float* Wv     = (const float*)d_in[5];
    const float* Wkn    = (const float*)d_in[6];
    const float* Wvn    = (const float*)d_in[7];
    const float* Wout   = (const float*)d_in[8];
    const float* bout   = (const float*)d_in[9];
    float* out = (float*)d_out;

    __nv_bfloat16 *hidh, *hidl, *wqh, *wql, *woh, *wol, *ath, *atl;
    float *qp;
    cudaGetSymbolAddress((void**)&hidh, g_hid_h);
    cudaGetSymbolAddress((void**)&hidl, g_hid_l);
    cudaGetSymbolAddress((void**)&wqh,  g_wq_h);
    cudaGetSymbolAddress((void**)&wql,  g_wq_l);
    cudaGetSymbolAddress((void**)&woh,  g_wo_h);
    cudaGetSymbolAddress((void**)&wol,  g_wo_l);
    cudaGetSymbolAddress((void**)&ath,  g_attn_h);
    cudaGetSymbolAddress((void**)&atl,  g_attn_l);
    cudaGetSymbolAddress((void**)&qp,   g_q);

    static int cfg_done = 0;
    const int gemm_smem = (2 * ABUF + 2 * ABUF + 2 * BBUF + 2 * BBUF) * 2;
    if (!cfg_done) {
        cudaFuncSetAttribute(gemm_bf3, cudaFuncAttributeMaxDynamicSharedMemorySize, gemm_smem);
        cudaFuncSetAttribute(qattn_lite, cudaFuncAttributeMaxDynamicSharedMemorySize, (int)sizeof(SmA));
        cfg_done = 1;
    }

    // split inputs/weights to bf16 hi/lo
    splitf<<<512, 512>>>(hidden, hidh, hidl, GM * GK);
    splitf<<<128, 512>>>(Wq,   wqh, wql, GK * GN);
    splitf<<<128, 512>>>(Wout, woh, wol, GK * GN);

    // K/V/KN/VN projections (fp32 split-K)
    proj_splitk<<<dim3(4, CNH, 16), 256>>>(enc, Wk, Wv, Wkn, Wvn);

    // Q = hidden @ Wq (tensor cores)
    gemm_bf3<<<dim3(GM / 128, GN / 128), 512, gemm_smem>>>(hidh, hidl, wqh, wql, nullptr, qp);

    // attention
    qattn_lite<<<dim3(CB * (CHW / 64), CNH / 2), 256, sizeof(SmA)>>>(idx);

    // out = attn @ Wout + bias (tensor cores)
    gemm_bf3<<<dim3(GM / 128, GN / 128), 512, gemm_smem>>>(ath, atl, woh, wol, bout, out);
}

// round 5
// speedup vs baseline: 2.9829x; 1.0711x over previous
#include <cuda_runtime.h>
#include <cuda_bf16.h>
#include <cstdint>

#define CB    2
#define CHW   4096
#define CHID  1280
#define CCAD  2048
#define CLTXT 77
#define CNT   4
#define CNH   20
#define CENCL (CLTXT + CNT)
#define KSLICE 512

#define GM 8192
#define GK 1280
#define GN 1280

// ---------------- scratch (device globals) ----------------
__device__ float g_q[(size_t)GM * GK];
__device__ float g_proj[(size_t)16 * CB * 80 * CHID];
__device__ __nv_bfloat16 g_hid_h[(size_t)GM * GK];
__device__ __nv_bfloat16 g_hid_l[(size_t)GM * GK];
__device__ __nv_bfloat16 g_wq_h[(size_t)GK * GN];
__device__ __nv_bfloat16 g_wq_l[(size_t)GK * GN];
__device__ __nv_bfloat16 g_wo_h[(size_t)GK * GN];
__device__ __nv_bfloat16 g_wo_l[(size_t)GK * GN];
__device__ __nv_bfloat16 g_attn_h[(size_t)GM * GK];
__device__ __nv_bfloat16 g_attn_l[(size_t)GM * GK];

// =====================================================================
// fp32 -> (hi, lo) bf16 split
// =====================================================================
__global__ __launch_bounds__(512) void splitf(
    const float* __restrict__ x,
    __nv_bfloat16* __restrict__ hi, __nv_bfloat16* __restrict__ lo, int n)
{
    for (int i = (blockIdx.x * 512 + threadIdx.x) * 4; i < n; i += gridDim.x * 512 * 4) {
        const float4 v = *(const float4*)(x + i);
        __nv_bfloat16 h0 = __float2bfloat16(v.x);
        __nv_bfloat16 h1 = __float2bfloat16(v.y);
        __nv_bfloat16 h2 = __float2bfloat16(v.z);
        __nv_bfloat16 h3 = __float2bfloat16(v.w);
        __nv_bfloat16 l0 = __float2bfloat16(v.x - __bfloat162float(h0));
        __nv_bfloat16 l1 = __float2bfloat16(v.y - __bfloat162float(h1));
        __nv_bfloat16 l2 = __float2bfloat16(v.z - __bfloat162float(h2));
        __nv_bfloat16 l3 = __float2bfloat16(v.w - __bfloat162float(h3));
        *(__nv_bfloat162*)(hi + i)     = __nv_bfloat162(h0, h1);
        *(__nv_bfloat162*)(hi + i + 2) = __nv_bfloat162(h2, h3);
        *(__nv_bfloat162*)(lo + i)     = __nv_bfloat162(l0, l1);
        *(__nv_bfloat162*)(lo + i + 2) = __nv_bfloat162(l2, l3);
    }
}

// =====================================================================
// bf16x3 mma.sync GEMM v2: C[GM,GN] = A@B (+bias), fp32 accum
// CTA 128x128, 512 thr (16 warps 4x4), warp tile 32x32, BK=32
// 4-stage cp.async ring, ONE __syncthreads per k-tile, pass-major mma.
// =====================================================================
#define CP_ASYNC(dst, src) asm volatile("cp.async.cg.shared.global [%0], [%1], 16;" :: "r"(dst), "l"(src))

__device__ __forceinline__ void ldsm4(uint32_t* r, uint32_t a) {
    asm volatile("ldmatrix.sync.aligned.m8n8.x4.shared.b16 {%0,%1,%2,%3}, [%4];"
        : "=r"(r[0]), "=r"(r[1]), "=r"(r[2]), "=r"(r[3]) : "r"(a));
}
__device__ __forceinline__ void ldsm4t(uint32_t* r, uint32_t a) {
    asm volatile("ldmatrix.sync.aligned.m8n8.x4.trans.shared.b16 {%0,%1,%2,%3}, [%4];"
        : "=r"(r[0]), "=r"(r[1]), "=r"(r[2]), "=r"(r[3]) : "r"(a));
}
__device__ __forceinline__ void mma16816(float* c, const uint32_t* a, const uint32_t* b) {
    asm volatile("mma.sync.aligned.m16n8k16.row.col.f32.bf16.bf16.f32 "
        "{%0,%1,%2,%3}, {%4,%5,%6,%7}, {%8,%9}, {%0,%1,%2,%3};"
        : "+f"(c[0]), "+f"(c[1]), "+f"(c[2]), "+f"(c[3])
        : "r"(a[0]), "r"(a[1]), "r"(a[2]), "r"(a[3]), "r"(b[0]), "r"(b[1]));
}

#define A_PITCH 40
#define B_PITCH 136
#define ABUF (128 * A_PITCH)     // elems per stage per array
#define BBUF (32 * B_PITCH)
#define NSTAGE 4
#define GEMM_SMEM ((2 * NSTAGE * ABUF + 2 * NSTAGE * BBUF) * 2)

__global__ __launch_bounds__(512, 1) void gemm_bf3(
    const __nv_bfloat16* __restrict__ Ahi, const __nv_bfloat16* __restrict__ Alo,
    const __nv_bfloat16* __restrict__ Bhi, const __nv_bfloat16* __restrict__ Blo,
    const float* __restrict__ bias, float* __restrict__ C)
{
    extern __shared__ __align__(16) char sm[];
    __nv_bfloat16* sAh = (__nv_bfloat16*)sm;           // [NSTAGE][ABUF]
    __nv_bfloat16* sAl = sAh + NSTAGE * ABUF;
    __nv_bfloat16* sBh = sAl + NSTAGE * ABUF;          // [NSTAGE][BBUF]
    __nv_bfloat16* sBl = sBh + NSTAGE * BBUF;

    const int tid = threadIdx.x;
    const int m0 = blockIdx.x * 128, n0 = blockIdx.y * 128;
    const int lane = tid & 31, warp = tid >> 5;
    const int wm = warp >> 2, wn = warp & 3;

    const int arow = tid >> 2, ak8 = (tid & 3) << 3;
    const int brow = tid >> 4, bn8 = (tid & 15) << 3;
    const __nv_bfloat16* gAh = Ahi + (size_t)(m0 + arow) * GK + ak8;
    const __nv_bfloat16* gAl = Alo + (size_t)(m0 + arow) * GK + ak8;
    const __nv_bfloat16* gBh = Bhi + (size_t)brow * GN + n0 + bn8;
    const __nv_bfloat16* gBl = Blo + (size_t)brow * GN + n0 + bn8;
    const uint32_t dAh = (uint32_t)__cvta_generic_to_shared(sAh) + (uint32_t)(arow * A_PITCH + ak8) * 2;
    const uint32_t dAl = (uint32_t)__cvta_generic_to_shared(sAl) + (uint32_t)(arow * A_PITCH + ak8) * 2;
    const uint32_t dBh = (uint32_t)__cvta_generic_to_shared(sBh) + (uint32_t)(brow * B_PITCH + bn8) * 2;
    const uint32_t dBl = (uint32_t)__cvta_generic_to_shared(sBl) + (uint32_t)(brow * B_PITCH + bn8) * 2;

#define LOADK(stage, kt) do {                                                   \
        const uint32_t ao_ = (uint32_t)(stage) * (ABUF * 2);                    \
        const uint32_t bo_ = (uint32_t)(stage) * (BBUF * 2);                    \
        const size_t kofs_ = (size_t)(kt) * 32;                                 \
        CP_ASYNC(dAh + ao_, gAh + kofs_);                                       \
        CP_ASYNC(dAl + ao_, gAl + kofs_);                                       \
        CP_ASYNC(dBh + bo_, gBh + kofs_ * GN);                                  \
        CP_ASYNC(dBl + bo_, gBl + kofs_ * GN);                                  \
        asm volatile("cp.async.commit_group;");                                 \
    } while (0)

    // prologue: stages 0..2
    LOADK(0, 0);
    LOADK(1, 1);
    LOADK(2, 2);

    float acc[2][4][4] = {};

    const uint32_t aOff = (uint32_t)((wm * 32 + (lane & 15)) * A_PITCH + ((lane >> 4) << 3)) * 2;
    const uint32_t aBh0 = (uint32_t)__cvta_generic_to_shared(sAh) + aOff;
    const uint32_t aBl0 = (uint32_t)__cvta_generic_to_shared(sAl) + aOff;
    const uint32_t bOff = (uint32_t)(((lane & 7) + ((lane >> 3) & 1) * 8) * B_PITCH
                                     + wn * 32 + ((lane >> 4) << 3)) * 2;
    const uint32_t bBh0 = (uint32_t)__cvta_generic_to_shared(sBh) + bOff;
    const uint32_t bBl0 = (uint32_t)__cvta_generic_to_shared(sBl) + bOff;

    const int NKT = GK / 32;   // 40
    for (int kt = 0; kt < NKT; kt++) {
        const int s = kt & (NSTAGE - 1);
        if (kt < NKT - 2)      asm volatile("cp.async.wait_group 2;");
        else if (kt == NKT - 2) asm volatile("cp.async.wait_group 1;");
        else                    asm volatile("cp.async.wait_group 0;");
        __syncthreads();   // single barrier per k-tile (see ring-safety argument)

        const uint32_t ah = aBh0 + s * (ABUF * 2);
        const uint32_t al = aBl0 + s * (ABUF * 2);
        const uint32_t bh = bBh0 + s * (BBUF * 2);
        const uint32_t bl = bBl0 + s * (BBUF * 2);
#pragma unroll
        for (int ks = 0; ks < 2; ks++) {
            const uint32_t ka  = ah + ks * 32;
            const uint32_t kal = al + ks * 32;
            const uint32_t kb  = bh + ks * (16 * B_PITCH * 2);
            const uint32_t kbl = bl + ks * (16 * B_PITCH * 2);
            uint32_t Ah0[4], Ah1[4], Al0[4], Al1[4];
            ldsm4(Ah0, ka);
            ldsm4(Ah1, ka + 16 * A_PITCH * 2);
            ldsm4(Al0, kal);
            ldsm4(Al1, kal + 16 * A_PITCH * 2);
            uint32_t Bh[8], Bl[8];
            ldsm4t(Bh,     kb);
            ldsm4t(Bh + 4, kb + 32);
            ldsm4t(Bl,     kbl);
            ldsm4t(Bl + 4, kbl + 32);
            // pass-major: 8 independent accumulators per pass
#pragma unroll
            for (int j = 0; j < 4; j++) {
                mma16816(acc[0][j], Ah0, &Bh[j * 2]);
                mma16816(acc[1][j], Ah1, &Bh[j * 2]);
            }
#pragma unroll
            for (int j = 0; j < 4; j++) {
                mma16816(acc[0][j], Ah0, &Bl[j * 2]);
                mma16816(acc[1][j], Ah1, &Bl[j * 2]);
            }
#pragma unroll
            for (int j = 0; j < 4; j++) {
                mma16816(acc[0][j], Al0, &Bh[j * 2]);
                mma16816(acc[1][j], Al1, &Bh[j * 2]);
            }
        }
        // refill the stage freed at kt-1 with chunk kt+3
        if (kt + 3 < NKT) {
            LOADK((kt + 3) & (NSTAGE - 1), kt + 3);
        }
    }

    // epilogue
#pragma unroll
    for (int fm = 0; fm < 2; fm++) {
        const int r0 = m0 + wm * 32 + fm * 16 + (lane >> 2);
#pragma unroll
        for (int j = 0; j < 4; j++) {
            const int cc = n0 + wn * 32 + j * 8 + ((lane & 3) << 1);
            float b0 = 0.f, b1 = 0.f;
            if (bias) { b0 = bias[cc]; b1 = bias[cc + 1]; }
            *(float2*)(C + (size_t)r0 * GN + cc) =
                make_float2(acc[fm][j][0] + b0, acc[fm][j][1] + b1);
            *(float2*)(C + (size_t)(r0 + 8) * GN + cc) =
                make_float2(acc[fm][j][2] + b0, acc[fm][j][3] + b1);
        }
    }
}

// =====================================================================
// Projections (K/V/KN/VN), split-K fp32 (unchanged)
// =====================================================================
__global__ __launch_bounds__(256) void proj_splitk(
    const float* __restrict__ enc,
    const float* __restrict__ Wk,  const float* __restrict__ Wv,
    const float* __restrict__ Wkn, const float* __restrict__ Wvn)
{
    __shared__ float As[16][68];
    __shared__ float Ws[16][64];
    const int type = blockIdx.z >> 2, split = blockIdx.z & 3;
    const int b = blockIdx.x >> 1, rowtile = blockIdx.x & 1;
    const int M = (type < 2) ? CLTXT : CNT;
    if (rowtile && M <= 64) return;
    const int col0 = blockIdx.y * 64;
    const int row0 = rowtile * 64;
    const float* W = (type == 0) ? Wk : (type == 1) ? Wv : (type == 2) ? Wkn : Wvn;
    const float* A = enc + (size_t)b * CENCL * CCAD + ((type >= 2) ? (size_t)CLTXT * CCAD : 0);
    float* C = g_proj + ((size_t)blockIdx.z * CB + b) * 80 * CHID;

    const int tid = threadIdx.x, tx = tid & 15, ty = tid >> 4;
    const int ar = tid >> 2, ak = (tid & 3) << 2;
    const int wk = tid >> 4, wc = (tid & 15) << 2;
    const bool aok = (row0 + ar) < M;
    const float* Aptr = A + (size_t)(row0 + ar) * CCAD + split * KSLICE + ak;
    const float* Wptr = W + (size_t)(split * KSLICE + wk) * CHID + col0 + wc;

    float acc[4][4] = {};
    for (int k0 = 0; k0 < KSLICE; k0 += 16) {
        float4 av = make_float4(0.f, 0.f, 0.f, 0.f);
        if (aok) av = *(const float4*)(Aptr + k0);
        As[ak + 0][ar] = av.x; As[ak + 1][ar] = av.y;
        As[ak + 2][ar] = av.z; As[ak + 3][ar] = av.w;
        *(float4*)&Ws[wk][wc] = *(const float4*)(Wptr + (size_t)k0 * CHID);
        __syncthreads();
#pragma unroll
        for (int kk = 0; kk < 16; kk++) {
            const float4 a4 = *(const float4*)&As[kk][ty * 4];
            const float4 b4 = *(const float4*)&Ws[kk][tx * 4];
            acc[0][0] += a4.x * b4.x; acc[0][1] += a4.x * b4.y; acc[0][2] += a4.x * b4.z; acc[0][3] += a4.x * b4.w;
            acc[1][0] += a4.y * b4.x; acc[1][1] += a4.y * b4.y; acc[1][2] += a4.y * b4.z; acc[1][3] += a4.y * b4.w;
            acc[2][0] += a4.z * b4.x; acc[2][1] += a4.z * b4.y; acc[2][2] += a4.z * b4.z; acc[2][3] += a4.z * b4.w;
            acc[3][0] += a4.w * b4.x; acc[3][1] += a4.w * b4.y; acc[3][2] += a4.w * b4.z; acc[3][3] += a4.w * b4.w;
        }
        __syncthreads();
    }
#pragma unroll
    for (int i = 0; i < 4; i++) {
        const int r = row0 + ty * 4 + i;
        if (r < M)
            *(float4*)(C + (size_t)r * CHID + col0 + tx * 4) =
                make_float4(acc[i][0], acc[i][1], acc[i][2], acc[i][3]);
    }
}

// =====================================================================
// Attention (Q from gmem), 2 heads/CTA; output bf16 hi/lo split
// =====================================================================
struct SmA {
    float Qs[2][64][68];
    float Ks[2][CLTXT][68];
    float Vs[2][CLTXT][68];
    float KNs[2][CNT][68];
    float VNs[2][CNT][68];
    float Wbuf[8][80];
};

__global__ __launch_bounds__(256, 1) void qattn_lite(const int* __restrict__ idx_alter)
{
    extern __shared__ char raw[];
    SmA& S = *reinterpret_cast<SmA*>(raw);
    const int b  = blockIdx.x >> 6;
    const int t0 = (blockIdx.x & 63) << 6;
    const int h0 = blockIdx.y * 2;
    const int tid = threadIdx.x;

    for (int i = tid; i < 64 * 32; i += 256) {
        const int t = i >> 5, c4 = (i & 31) << 2;
        const int hh = c4 >> 6, d = c4 & 63;
        float4 q = *(const float4*)(g_q + ((size_t)b * CHW + t0 + t) * CHID + h0 * 64 + c4);
        q.x *= 0.125f; q.y *= 0.125f; q.z *= 0.125f; q.w *= 0.125f;
        *(float4*)&S.Qs[hh][t][d] = q;
    }

#pragma unroll
    for (int hh = 0; hh < 2; hh++) {
        const size_t cb = (size_t)(h0 + hh) * 64;
        for (int i = tid; i < CLTXT * 16; i += 256) {
            const int j = i >> 4, d4 = (i & 15) << 2;
            float4 sk = make_float4(0.f, 0.f, 0.f, 0.f);
            float4 sv = make_float4(0.f, 0.f, 0.f, 0.f);
#pragma unroll
            for (int s = 0; s < 4; s++) {
                const float4 k4 = *(const float4*)(g_proj + ((size_t)(0 + s) * CB + b) * 80 * CHID + (size_t)j * CHID + cb + d4);
                const float4 v4 = *(const float4*)(g_proj + ((size_t)(4 + s) * CB + b) * 80 * CHID + (size_t)j * CHID + cb + d4);
                sk.x += k4.x; sk.y += k4.y; sk.z += k4.z; sk.w += k4.w;
                sv.x += v4.x; sv.y += v4.y; sv.z += v4.z; sv.w += v4.w;
            }
            *(float4*)&S.Ks[hh][j][d4] = sk;
            *(float4*)&S.Vs[hh][j][d4] = sv;
        }
        for (int i = tid; i < CNT * 16; i += 256) {
            const int j = i >> 4, d4 = (i & 15) << 2;
            float4 sk = make_float4(0.f, 0.f, 0.f, 0.f);
            float4 sv = make_float4(0.f, 0.f, 0.f, 0.f);
#pragma unroll
            for (int s = 0; s < 4; s++) {
                const float4 k4 = *(const float4*)(g_proj + ((size_t)(8  + s) * CB + b) * 80 * CHID + (size_t)j * CHID + cb + d4);
                const float4 v4 = *(const float4*)(g_proj + ((size_t)(12 + s) * CB + b) * 80 * CHID + (size_t)j * CHID + cb + d4);
                sk.x += k4.x; sk.y += k4.y; sk.z += k4.z; sk.w += k4.w;
                sv.x += v4.x; sv.y += v4.y; sv.z += v4.z; sv.w += v4.w;
            }
            *(float4*)&S.KNs[hh][j][d4] = sk;
            *(float4*)&S.VNs[hh][j][d4] = sv;
        }
    }
    const int sidx = idx_alter[b];
    __syncthreads();

    const int warp = tid >> 5, lane = tid & 31;
    const int j0 = lane, j1 = lane + 32, j2 = lane + 64;
    const int j2c = (j2 < CLTXT) ? j2 : 0;
    float* wrow = S.Wbuf[warp];

#pragma unroll
    for (int hh = 0; hh < 2; hh++) {
        const float* k0p = S.Ks[hh][j0];
        const float* k1p = S.Ks[hh][j1];
        const float* k2p = S.Ks[hh][j2c];
        const float* knp = S.KNs[hh][lane & 3];

        for (int it = 0; it < 8; ++it) {
            const int t = warp * 8 + it;
            const float* qrow = S.Qs[hh][t];
            float l0 = 0.f, l1 = 0.f, l2 = 0.f, ln = 0.f;
#pragma unroll
            for (int d4 = 0; d4 < 64; d4 += 4) {
                const float4 q  = *(const float4*)(qrow + d4);
                const float4 x  = *(const float4*)(k0p + d4);
                const float4 y  = *(const float4*)(k1p + d4);
                const float4 z  = *(const float4*)(k2p + d4);
                const float4 w4 = *(const float4*)(knp + d4);
                l0 += q.x * x.x + q.y * x.y + q.z * x.z + q.w * x.w;
                l1 += q.x * y.x + q.y * y.y + q.z * y.z + q.w * y.w;
                l2 += q.x * z.x + q.y * z.y + q.z * z.z + q.w * z.w;
                ln += q.x * w4.x + q.y * w4.y + q.z * w4.z + q.w * w4.w;
            }
            if (j2 >= CLTXT) l2 = -1e30f;

            float lm = fmaxf(fmaxf(l0, l1), l2);
#pragma unroll
            for (int o = 16; o; o >>= 1) lm = fmaxf(lm, __shfl_xor_sync(0xffffffffu, lm, o));
            const float e0 = __expf(l0 - lm);
            const float e1 = __expf(l1 - lm);
            const float e2 = (j2 < CLTXT) ? __expf(l2 - lm) : 0.f;
            float es = e0 + e1 + e2;
#pragma unroll
            for (int o = 16; o; o >>= 1) es += __shfl_xor_sync(0xffffffffu, es, o);
            const float inv = 1.f / es;
            wrow[j0] = e0 * inv;
            wrow[j1] = e1 * inv;
            if (j2 < CLTXT) wrow[j2] = e2 * inv;

            if (lane >= CNT) ln = -1e30f;
            float mn = ln;
            mn = fmaxf(mn, __shfl_xor_sync(0xffffffffu, mn, 1));
            mn = fmaxf(mn, __shfl_xor_sync(0xffffffffu, mn, 2));
            const float en = __expf(ln - mn);
            float sn = en;
            sn += __shfl_xor_sync(0xffffffffu, sn, 1);
            sn += __shfl_xor_sync(0xffffffffu, sn, 2);
            const float wnv = en / sn;
            const float wn0 = __shfl_sync(0xffffffffu, wnv, 0);
            const float wn1 = __shfl_sync(0xffffffffu, wnv, 1);
            const float wn2 = __shfl_sync(0xffffffffu, wnv, 2);
            const float wn3 = __shfl_sync(0xffffffffu, wnv, 3);
            __syncwarp();

            const int d0 = lane << 1;
            const float2 a0 = *(const float2*)&S.VNs[hh][0][d0];
            const float2 a1 = *(const float2*)&S.VNs[hh][1][d0];
            const float2 a2 = *(const float2*)&S.VNs[hh][2][d0];
            const float2 a3 = *(const float2*)&S.VNs[hh][3][d0];
            const float vix = wn0 * a0.x + wn1 * a1.x + wn2 * a2.x + wn3 * a3.x;
            const float viy = wn0 * a0.y + wn1 * a1.y + wn2 * a2.y + wn3 * a3.y;

            float bx = 0.f, by = 0.f;
#pragma unroll 7
            for (int j = 0; j < CLTXT; j++) {
                const float wj = wrow[j];
                const float2 vv = *(const float2*)&S.Vs[hh][j][d0];
                bx += wj * vv.x; by += wj * vv.y;
            }
            const float wsel = wrow[sidx];
            const float2 vsel = *(const float2*)&S.Vs[hh][sidx][d0];
            const float ox = bx + wsel * (vix - vsel.x);
            const float oy = by + wsel * (viy - vsel.y);

            const size_t off = ((size_t)b * CHW + t0 + t) * CHID + (h0 + hh) * 64 + d0;
            const __nv_bfloat16 hx = __float2bfloat16(ox);
            const __nv_bfloat16 hy = __float2bfloat16(oy);
            const __nv_bfloat16 lx = __float2bfloat16(ox - __bfloat162float(hx));
            const __nv_bfloat16 ly = __float2bfloat16(oy - __bfloat162float(hy));
            *(__nv_bfloat162*)(g_attn_h + off) = __nv_bfloat162(hx, hy);
            *(__nv_bfloat162*)(g_attn_l + off) = __nv_bfloat162(lx, ly);
            __syncwarp();
        }
    }
}

// ---------------- launch ----------------
extern "C" void kernel_launch(void* const* d_in, const int* in_sizes, int n_in,
                              void* d_out, int out_size)
{
    (void)in_sizes; (void)n_in; (void)out_size;
    const float* hidden = (const float*)d_in[0];
    const float* enc    = (const float*)d_in[1];
    const int*   idx    = (const int*)  d_in[2];
    const float* Wq     = (const float*)d_in[3];
    const float* Wk     = (const float*)d_in[4];
    const float* Wv     = (const float*)d_in[5];
    const float* Wkn    = (const float*)d_in[6];
    const float* Wvn    = (const float*)d_in[7];
    const float* Wout   = (const float*)d_in[8];
    const float* bout   = (const float*)d_in[9];
    float* out = (float*)d_out;

    __nv_bfloat16 *hidh, *hidl, *wqh, *wql, *woh, *wol, *ath, *atl;
    float* qp;
    cudaGetSymbolAddress((void**)&hidh, g_hid_h);
    cudaGetSymbolAddress((void**)&hidl, g_hid_l);
    cudaGetSymbolAddress((void**)&wqh,  g_wq_h);
    cudaGetSymbolAddress((void**)&wql,  g_wq_l);
    cudaGetSymbolAddress((void**)&woh,  g_wo_h);
    cudaGetSymbolAddress((void**)&wol,  g_wo_l);
    cudaGetSymbolAddress((void**)&ath,  g_attn_h);
    cudaGetSymbolAddress((void**)&atl,  g_attn_l);
    cudaGetSymbolAddress((void**)&qp,   g_q);

    cudaFuncSetAttribute(gemm_bf3, cudaFuncAttributeMaxDynamicSharedMemorySize, GEMM_SMEM);
    cudaFuncSetAttribute(qattn_lite, cudaFuncAttributeMaxDynamicSharedMemorySize, (int)sizeof(SmA));

    // splits
    splitf<<<512, 512>>>(hidden, hidh, hidl, GM * GK);
    splitf<<<128, 512>>>(Wq,   wqh, wql, GK * GN);
    splitf<<<128, 512>>>(Wout, woh, wol, GK * GN);

    // K/V/KN/VN projections
    proj_splitk<<<dim3(4, CNH, 16), 256>>>(enc, Wk, Wv, Wkn, Wvn);

    // Q = hidden @ Wq
    gemm_bf3<<<dim3(GM / 128, GN / 128), 512, GEMM_SMEM>>>(hidh, hidl, wqh, wql, nullptr, qp);

    // attention
    qattn_lite<<<dim3(CB * (CHW / 64), CNH / 2), 256, sizeof(SmA)>>>(idx);

    // out = attn @ Wout + bias
    gemm_bf3<<<dim3(GM / 128, GN / 128), 512, GEMM_SMEM>>>(ath, atl, woh, wol, bout, out);
}